// round 14
// baseline (speedup 1.0000x reference)
#include <cuda_runtime.h>
#include <math.h>

#define NU 4096
#define NI 4096
#define NN 8192
#define D  128
#define KNN 10
#define PPRK 20
#define MAXDEG 256
#define KCAP 128
#define DEGCAP 96
#define NCHUNK 4
#define UCH 1024
#define DELTA 0.15f
#define ONEM  0.85f

// ---------- static device scratch ----------
__device__ float g_xn[(size_t)NN * D];
__device__ float g_sim[(size_t)NU * NI];       // knn chain only
__device__ float g_scores[(size_t)NU * NI];    // ppr chain only
__device__ float g_piA[(size_t)NN * NU];
__device__ float g_piB[(size_t)NN * NU];
__device__ int   g_uitems[NU * MAXDEG];
__device__ int   g_iusers[NI * MAXDEG];
__device__ int   g_ucnt[NU];
__device__ int   g_icnt[NI];
__device__ float g_invdeg[NN];
__device__ float g_dinv[NN];
// knn edge lists (global node ids in col)
__device__ int   g_knn_cnt[NN];
__device__ int   g_knn_col[(size_t)NN * KCAP];
__device__ float g_knn_w[(size_t)NN * KCAP];
__device__ float g_knnsum[NN];
// ppr extra edges (user-side only; item-side is a scatter)
__device__ int   g_extra_it[NU * PPRK];
__device__ float g_extra_w[NU * PPRK];
__device__ float g_extra_isum[NI];

// ---------- zero all counters ----------
__global__ void zero_counts_kernel() {
    int i = blockIdx.x * 256 + threadIdx.x;   // 0..8191
    g_knn_cnt[i] = 0;
    if (i < NU) g_ucnt[i] = 0;
    if (i < NI) {
        g_icnt[i] = 0;
        g_extra_isum[i] = 0.0f;
    }
}

// ---------- row-normalize features ----------
__global__ void normalize_kernel(const float* __restrict__ fu, const float* __restrict__ fi) {
    int row = blockIdx.x;
    int t = threadIdx.x; // 128 threads
    const float* src = (row < NU) ? &fu[(size_t)row * D] : &fi[(size_t)(row - NU) * D];
    float v = src[t];
    float s = v * v;
    #pragma unroll
    for (int o = 16; o; o >>= 1) s += __shfl_xor_sync(0xffffffff, s, o);
    __shared__ float ws[4];
    if ((t & 31) == 0) ws[t >> 5] = s;
    __syncthreads();
    float tot = ws[0] + ws[1] + ws[2] + ws[3];
    g_xn[(size_t)row * D + t] = v / fmaxf(sqrtf(tot), 1e-12f);
}

// ---------- SYRK: sim = Xn Xn^T (streaming stores; don't pollute L2) ----------
__global__ void __launch_bounds__(256) syrk_kernel(int base) {
    int bm = blockIdx.y * 128, bn = blockIdx.x * 128;
    if (bn < bm) return;
    __shared__ float As[16][132];
    __shared__ float Bs[16][132];
    int tid = threadIdx.x;
    int tx = tid & 15, ty = tid >> 4;
    const float* X = g_xn + (size_t)base * D;
    float acc[8][8] = {};
    for (int k0 = 0; k0 < D; k0 += 16) {
        #pragma unroll
        for (int l = 0; l < 2; ++l) {
            int idx = tid * 2 + l;
            int rr  = idx >> 2;
            int c4  = (idx & 3) * 4;
            float4 a = *(const float4*)&X[(size_t)(bm + rr) * D + k0 + c4];
            As[c4 + 0][rr] = a.x; As[c4 + 1][rr] = a.y;
            As[c4 + 2][rr] = a.z; As[c4 + 3][rr] = a.w;
            float4 b = *(const float4*)&X[(size_t)(bn + rr) * D + k0 + c4];
            Bs[c4 + 0][rr] = b.x; Bs[c4 + 1][rr] = b.y;
            Bs[c4 + 2][rr] = b.z; Bs[c4 + 3][rr] = b.w;
        }
        __syncthreads();
        #pragma unroll
        for (int k = 0; k < 16; ++k) {
            float a[8], b[8];
            *(float4*)&a[0] = *(const float4*)&As[k][ty * 8];
            *(float4*)&a[4] = *(const float4*)&As[k][ty * 8 + 4];
            *(float4*)&b[0] = *(const float4*)&Bs[k][tx * 8];
            *(float4*)&b[4] = *(const float4*)&Bs[k][tx * 8 + 4];
            #pragma unroll
            for (int i = 0; i < 8; ++i)
                #pragma unroll
                for (int j = 0; j < 8; ++j) acc[i][j] = fmaf(a[i], b[j], acc[i][j]);
        }
        __syncthreads();
    }
    #pragma unroll
    for (int i = 0; i < 8; ++i) {
        size_t ro = (size_t)(bm + ty * 8 + i) * NI + bn + tx * 8;
        __stcs((float4*)&g_sim[ro],     make_float4(acc[i][0], acc[i][1], acc[i][2], acc[i][3]));
        __stcs((float4*)&g_sim[ro + 4], make_float4(acc[i][4], acc[i][5], acc[i][6], acc[i][7]));
    }
    if (bm != bn) {
        #pragma unroll
        for (int j = 0; j < 8; ++j) {
            size_t ro = (size_t)(bn + tx * 8 + j) * NI + bm + ty * 8;
            __stcs((float4*)&g_sim[ro],     make_float4(acc[0][j], acc[1][j], acc[2][j], acc[3][j]));
            __stcs((float4*)&g_sim[ro + 4], make_float4(acc[4][j], acc[5][j], acc[6][j], acc[7][j]));
        }
    }
}

// ---------- KNN top-K with cached per-thread argmax; edges to lists ----------
__global__ void __launch_bounds__(256) knn_topk_kernel(int base) {
    int row = blockIdx.x, t = threadIdx.x;
    float v[16];
    const float* srow = g_sim + (size_t)row * NI;
    #pragma unroll
    for (int p = 0; p < 16; ++p) {
        int c = t + p * 256;
        float x = __ldcs(&srow[c]);
        v[p] = (c == row) ? -INFINITY : x;
    }
    float bv = v[0]; int bp = 0;
    #pragma unroll
    for (int p = 1; p < 16; ++p) if (v[p] > bv) { bv = v[p]; bp = p; }

    __shared__ float swv[8];
    __shared__ int   swi[8];
    __shared__ int   bsel;
    for (int k = 0; k < KNN; ++k) {
        float wv = bv; int wc = t + bp * 256;
        #pragma unroll
        for (int o = 16; o; o >>= 1) {
            float ov = __shfl_xor_sync(0xffffffff, wv, o);
            int   oc = __shfl_xor_sync(0xffffffff, wc, o);
            if (ov > wv || (ov == wv && oc < wc)) { wv = ov; wc = oc; }
        }
        if ((t & 31) == 0) { swv[t >> 5] = wv; swi[t >> 5] = wc; }
        __syncthreads();
        if (t == 0) {
            float BV = swv[0]; int BC = swi[0];
            #pragma unroll
            for (int w = 1; w < 8; ++w)
                if (swv[w] > BV || (swv[w] == BV && swi[w] < BC)) { BV = swv[w]; BC = swi[w]; }
            bsel = BC;
            float wgt = fminf(fmaxf((BV + 1.0f) * 0.5f, 1e-6f), 1.0f);
            int gi = base + row, gj = base + BC;
            int a = atomicAdd(&g_knn_cnt[gi], 1);
            if (a < KCAP) { g_knn_col[(size_t)gi * KCAP + a] = gj; g_knn_w[(size_t)gi * KCAP + a] = wgt; }
            int b = atomicAdd(&g_knn_cnt[gj], 1);
            if (b < KCAP) { g_knn_col[(size_t)gj * KCAP + b] = gi; g_knn_w[(size_t)gj * KCAP + b] = wgt; }
        }
        __syncthreads();
        int sc = bsel;
        if ((sc & 255) == t) {
            v[sc >> 8] = -INFINITY;
            bv = v[0]; bp = 0;
            #pragma unroll
            for (int p = 1; p < 16; ++p) if (v[p] > bv) { bv = v[p]; bp = p; }
        }
    }
}

// ---------- bipartite adjacency lists (float4 reads) ----------
__global__ void build_lists_kernel(const float* __restrict__ r) {
    int u = blockIdx.x, t = threadIdx.x;
    __shared__ int scnt;
    if (t == 0) scnt = 0;
    __syncthreads();
    const float4* rr = (const float4*)(r + (size_t)u * NI);
    for (int c4 = t; c4 < NI / 4; c4 += 256) {
        float4 x = __ldcs(&rr[c4]);
        #pragma unroll
        for (int b = 0; b < 4; ++b) {
            float xv = (b == 0) ? x.x : (b == 1) ? x.y : (b == 2) ? x.z : x.w;
            if (xv > 0.0f) {
                int c = c4 * 4 + b;
                int p = atomicAdd(&scnt, 1);
                if (p < MAXDEG) g_uitems[u * MAXDEG + p] = c;
                int q = atomicAdd(&g_icnt[c], 1);
                if (q < MAXDEG) g_iusers[c * MAXDEG + q] = u;
            }
        }
    }
    __syncthreads();
    if (t == 0) g_ucnt[u] = scnt;
}

__global__ void invdeg_kernel() {
    int j = blockIdx.x * 256 + threadIdx.x;
    if (j < NN) {
        int c = (j < NU) ? g_ucnt[j] : g_icnt[j - NU];
        g_invdeg[j] = 1.0f / (float)(c + 1);
    }
}

__global__ void zero_piA_kernel() {
    size_t i = (size_t)blockIdx.x * 256 + threadIdx.x;
    float4 z = make_float4(0.f, 0.f, 0.f, 0.f);
    float4* p = (float4*)g_piA;
    size_t total = (size_t)NN * NU / 4;
    for (size_t k = i; k < total; k += (size_t)gridDim.x * 256) p[k] = z;
}

// ---------- build pi2 analytically (per-chunk: writes column ubase+blockIdx.x) ----------
__global__ void pi2_build_kernel(int ubase) {
    int u = ubase + blockIdx.x, t = threadIdx.x;
    int lane = t & 31, wid = t >> 5;
    __shared__ int items[MAXDEG];
    __shared__ int du_s;
    if (t == 0) du_s = min(g_ucnt[u], MAXDEG);
    __syncthreads();
    int d = du_s;
    for (int l = t; l < d; l += 256) items[l] = g_uitems[u * MAXDEG + l];
    __syncthreads();
    float duv = g_invdeg[u];
    float v0 = 0.85f * duv + 0.15f;
    float vI = 0.85f * duv;
    if (t == 0) atomicAdd(&g_piA[(size_t)u * NU + u], 0.85f * v0 * duv + 0.15f);
    for (int l = t; l < d; l += 256) {
        int m = NU + items[l];
        atomicAdd(&g_piA[(size_t)m * NU + u], 0.85f * v0 * duv);
    }
    for (int l = wid; l < d; l += 8) {
        int it = items[l];
        float div = g_invdeg[NU + it];
        float add = 0.85f * vI * div;
        if (lane == 0) atomicAdd(&g_piA[(size_t)(NU + it) * NU + u], add);
        int cj = min(g_icnt[it], MAXDEG);
        for (int q = lane; q < cj; q += 32) {
            int up = g_iusers[it * MAXDEG + q];
            atomicAdd(&g_piA[(size_t)up * NU + u], add);
        }
    }
}

// ---------- dense PPR step, u-chunked (1024 columns per launch) ----------
__global__ void __launch_bounds__(256) ppr_step_kernel(int flip, int jbase, int ubase) {
    const float* __restrict__ pin = flip ? g_piB : g_piA;
    float* __restrict__ pout      = flip ? g_piA : g_piB;
    int j = jbase + blockIdx.x;
    int t = threadIdx.x;
    __shared__ int   nbr[MAXDEG];
    __shared__ float nw[MAXDEG];
    __shared__ int   Ls;
    if (t == 0) Ls = min((j < NU) ? g_ucnt[j] : g_icnt[j - NU], MAXDEG);
    __syncthreads();
    int L = Ls;
    if (j < NU) { if (t < L) nbr[t] = NU + g_uitems[j * MAXDEG + t]; }
    else        { if (t < L) nbr[t] = g_iusers[(j - NU) * MAXDEG + t]; }
    __syncthreads();
    if (t < L) nw[t] = g_invdeg[nbr[t]];
    __syncthreads();

    int u0 = ubase + t * 4;
    float dj = g_invdeg[j];
    float4 p = *(const float4*)(pin + (size_t)j * NU + u0);
    float ax = p.x * dj, ay = p.y * dj, az = p.z * dj, aw = p.w * dj;
    for (int l = 0; l < L; ++l) {
        float4 q = *(const float4*)(pin + (size_t)nbr[l] * NU + u0);
        float w = nw[l];
        ax = fmaf(q.x, w, ax); ay = fmaf(q.y, w, ay);
        az = fmaf(q.z, w, az); aw = fmaf(q.w, w, aw);
    }
    ax *= ONEM; ay *= ONEM; az *= ONEM; aw *= ONEM;
    if (j < NU) {
        int du = j - u0;
        if (du == 0) ax += DELTA;
        else if (du == 1) ay += DELTA;
        else if (du == 2) az += DELTA;
        else if (du == 3) aw += DELTA;
    }
    *(float4*)(pout + (size_t)j * NU + u0) = make_float4(ax, ay, az, aw);
}

// ---------- fused final PPR step (item rows) + in-tile mask + transpose ----------
// grid: (NI/32, UCH/128) per chunk. Reads pi4 from g_piA. Per-element FMA order
// identical to ppr_step_kernel; rated (u,item) cells set to -inf before store.
__global__ void __launch_bounds__(256) ppr_item_T_kernel(int ubase) {
    int i0 = blockIdx.x * 32;                 // item tile
    int u0 = ubase + blockIdx.y * 128;        // user-column tile
    int t = threadIdx.x;
    int w = t >> 5, lane = t & 31;
    __shared__ int   sdeg[32];
    __shared__ int   snbr[32][DEGCAP];
    __shared__ float snw[32][DEGCAP];
    __shared__ float stile[32][132];   // [item-within-tile][u-within-tile]
    if (t < 32) sdeg[t] = min(g_icnt[i0 + t], DEGCAP);
    __syncthreads();
    for (int idx = t; idx < 32 * DEGCAP; idx += 256) {
        int rr = idx / DEGCAP, l = idx - rr * DEGCAP;
        if (l < sdeg[rr]) {
            int up = g_iusers[(i0 + rr) * MAXDEG + l];
            snbr[rr][l] = up;
            snw[rr][l]  = g_invdeg[up];
        }
    }
    __syncthreads();
    const float* __restrict__ pin = g_piA;
    for (int rr = w; rr < 32; rr += 8) {
        int j = NU + i0 + rr;
        float dj = g_invdeg[j];
        float4 p = *(const float4*)(pin + (size_t)j * NU + u0 + lane * 4);
        float ax = p.x * dj, ay = p.y * dj, az = p.z * dj, aw = p.w * dj;
        int L = sdeg[rr];
        for (int l = 0; l < L; ++l) {
            float4 q = *(const float4*)(pin + (size_t)snbr[rr][l] * NU + u0 + lane * 4);
            float wl = snw[rr][l];
            ax = fmaf(q.x, wl, ax); ay = fmaf(q.y, wl, ay);
            az = fmaf(q.z, wl, az); aw = fmaf(q.w, wl, aw);
        }
        stile[rr][lane * 4 + 0] = ax * ONEM;
        stile[rr][lane * 4 + 1] = ay * ONEM;
        stile[rr][lane * 4 + 2] = az * ONEM;
        stile[rr][lane * 4 + 3] = aw * ONEM;
    }
    __syncthreads();
    // in-tile mask: rated (u, item) -> -inf
    for (int rr = w; rr < 32; rr += 8) {
        int L = sdeg[rr];
        for (int l = lane; l < L; l += 32) {
            int up = snbr[rr][l];
            int du = up - u0;
            if (du >= 0 && du < 128) stile[rr][du] = -INFINITY;
        }
    }
    __syncthreads();
    // write transposed: g_scores[u0+ur][i0 + part*16 .. +15]
    int ur = t >> 1, part = t & 1;
    float vals[16];
    #pragma unroll
    for (int c = 0; c < 16; ++c) vals[c] = stile[part * 16 + c][ur];
    float4* dst = (float4*)(g_scores + (size_t)(u0 + ur) * NI + i0 + part * 16);
    dst[0] = make_float4(vals[0], vals[1], vals[2], vals[3]);
    dst[1] = make_float4(vals[4], vals[5], vals[6], vals[7]);
    dst[2] = make_float4(vals[8], vals[9], vals[10], vals[11]);
    dst[3] = make_float4(vals[12], vals[13], vals[14], vals[15]);
}

// ---------- PPR top-K -> user-side extra edge lists (per-chunk) ----------
__global__ void __launch_bounds__(256) ppr_topk_kernel(int ubase) {
    int u = ubase + blockIdx.x, t = threadIdx.x;
    float v[16];
    const float* srow = g_scores + (size_t)u * NI;
    #pragma unroll
    for (int p = 0; p < 16; ++p) v[p] = srow[t + p * 256];
    float bv = v[0]; int bp = 0;
    #pragma unroll
    for (int p = 1; p < 16; ++p) if (v[p] > bv) { bv = v[p]; bp = p; }

    __shared__ float swv[8];
    __shared__ int   swi[8];
    __shared__ float selv[PPRK];
    __shared__ int   seli[PPRK];
    __shared__ int   bsel;
    for (int k = 0; k < PPRK; ++k) {
        float wv = bv; int wc = t + bp * 256;
        #pragma unroll
        for (int o = 16; o; o >>= 1) {
            float ov = __shfl_xor_sync(0xffffffff, wv, o);
            int   oc = __shfl_xor_sync(0xffffffff, wc, o);
            if (ov > wv || (ov == wv && oc < wc)) { wv = ov; wc = oc; }
        }
        if ((t & 31) == 0) { swv[t >> 5] = wv; swi[t >> 5] = wc; }
        __syncthreads();
        if (t == 0) {
            float BV = swv[0]; int BC = swi[0];
            #pragma unroll
            for (int w = 1; w < 8; ++w)
                if (swv[w] > BV || (swv[w] == BV && swi[w] < BC)) { BV = swv[w]; BC = swi[w]; }
            selv[k] = BV; seli[k] = BC; bsel = BC;
        }
        __syncthreads();
        int sc = bsel;
        if ((sc & 255) == t) {
            v[sc >> 8] = -INFINITY;
            bv = v[0]; bp = 0;
            #pragma unroll
            for (int p = 1; p < 16; ++p) if (v[p] > bv) { bv = v[p]; bp = p; }
        }
    }
    if (t < PPRK) {
        float w  = fmaxf(selv[t], 0.0f);
        float mx = fmaxf(selv[0], 0.0f);
        if (mx > 0.0f) w = w / fmaxf(mx, 1e-12f);
        int it = seli[t];
        g_extra_it[u * PPRK + t] = it;
        g_extra_w[u * PPRK + t]  = w;
        atomicAdd(&g_extra_isum[it], w);
    }
}

// ---------- dedup'd KNN list sums (one warp per node) ----------
__global__ void knn_sum_kernel() {
    int node = blockIdx.x * 8 + (threadIdx.x >> 5);
    int lane = threadIdx.x & 31;
    int c = min(g_knn_cnt[node], KCAP);
    const int*   col = g_knn_col + (size_t)node * KCAP;
    const float* w   = g_knn_w   + (size_t)node * KCAP;
    float s = 0.0f;
    for (int e = lane; e < c; e += 32) {
        int cc = col[e];
        bool dup = false;
        for (int q = 0; q < e; ++q) if (col[q] == cc) { dup = true; break; }
        if (!dup) s += w[e];
    }
    #pragma unroll
    for (int o = 16; o; o >>= 1) s += __shfl_xor_sync(0xffffffff, s, o);
    if (lane == 0) g_knnsum[node] = s;
}

// ---------- total rowsum -> dinv (r sums = counts, since r is binary) ----------
__global__ void dinv_kernel() {
    int i = blockIdx.x * 256 + threadIdx.x;   // 0..8191
    float s = g_knnsum[i];
    if (i < NU) {
        s += (float)g_ucnt[i];
        #pragma unroll
        for (int k = 0; k < PPRK; ++k) s += g_extra_w[i * PPRK + k];
    } else {
        s += (float)g_icnt[i - NU] + g_extra_isum[i - NU];
    }
    g_dinv[i] = (s > 0.0f) ? rsqrtf(fmaxf(s, 1e-12f)) : 0.0f;
}

// ---------- write user rows (full row, scaled; no r read) ----------
__global__ void __launch_bounds__(256) write_user_kernel(float* __restrict__ out) {
    int u = blockIdx.x, t = threadIdx.x;
    __shared__ float bufUU[NU];
    __shared__ float bufUI[NI];
    float4 z = make_float4(0.f, 0.f, 0.f, 0.f);
    #pragma unroll
    for (int q = t; q < NU / 4; q += 256) { ((float4*)bufUU)[q] = z; ((float4*)bufUI)[q] = z; }
    __syncthreads();
    int c = min(g_knn_cnt[u], KCAP);
    for (int l = t; l < c; l += 256) bufUU[g_knn_col[(size_t)u * KCAP + l]] = g_knn_w[(size_t)u * KCAP + l];
    int d = min(g_ucnt[u], MAXDEG);
    for (int l = t; l < d; l += 256) bufUI[g_uitems[u * MAXDEG + l]] = 1.0f;
    if (t < PPRK) bufUI[g_extra_it[u * PPRK + t]] = g_extra_w[u * PPRK + t];
    __syncthreads();
    float du = g_dinv[u];
    size_t rowo = (size_t)u * NN;
    for (int q = t; q < NU / 4; q += 256) {
        float4 b  = ((float4*)bufUU)[q];
        float4 dv = *(const float4*)&g_dinv[q * 4];
        ((float4*)&out[rowo])[q] = make_float4(b.x * du * dv.x, b.y * du * dv.y,
                                               b.z * du * dv.z, b.w * du * dv.w);
    }
    for (int q = t; q < NI / 4; q += 256) {
        float4 b  = ((float4*)bufUI)[q];
        float4 dv = *(const float4*)&g_dinv[NU + q * 4];
        ((float4*)&out[rowo + NU])[q] = make_float4(b.x * du * dv.x, b.y * du * dv.y,
                                                    b.z * du * dv.z, b.w * du * dv.w);
    }
}

// ---------- write item rows (IU from rated users; extras patched after) ----------
__global__ void __launch_bounds__(256) write_item_kernel(float* __restrict__ out) {
    int i = blockIdx.x, t = threadIdx.x;
    int node = NU + i;
    __shared__ float bufIU[NU];
    __shared__ float bufII[NI];
    float4 z = make_float4(0.f, 0.f, 0.f, 0.f);
    #pragma unroll
    for (int q = t; q < NU / 4; q += 256) { ((float4*)bufIU)[q] = z; ((float4*)bufII)[q] = z; }
    __syncthreads();
    int c = min(g_knn_cnt[node], KCAP);
    for (int l = t; l < c; l += 256)
        bufII[g_knn_col[(size_t)node * KCAP + l] - NU] = g_knn_w[(size_t)node * KCAP + l];
    int d = min(g_icnt[i], MAXDEG);
    for (int l = t; l < d; l += 256) bufIU[g_iusers[i * MAXDEG + l]] = 1.0f;
    __syncthreads();
    float dn = g_dinv[node];
    size_t rowo = (size_t)node * NN;
    for (int q = t; q < NU / 4; q += 256) {
        float4 b  = ((float4*)bufIU)[q];
        float4 dv = *(const float4*)&g_dinv[q * 4];
        ((float4*)&out[rowo])[q] = make_float4(b.x * dn * dv.x, b.y * dn * dv.y,
                                               b.z * dn * dv.z, b.w * dn * dv.w);
    }
    for (int q = t; q < NI / 4; q += 256) {
        float4 b  = ((float4*)bufII)[q];
        float4 dv = *(const float4*)&g_dinv[NU + q * 4];
        ((float4*)&out[rowo + NU])[q] = make_float4(b.x * dn * dv.x, b.y * dn * dv.y,
                                                    b.z * dn * dv.z, b.w * dn * dv.w);
    }
}

// ---------- scatter extras into IU quadrant (user-side, uncapped) ----------
__global__ void extra_IU_kernel(float* __restrict__ out) {
    int u = blockIdx.x, t = threadIdx.x;
    if (t < PPRK) {
        int it = g_extra_it[u * PPRK + t];
        float w = g_extra_w[u * PPRK + t];
        out[(size_t)(NU + it) * NN + u] = w * g_dinv[NU + it] * g_dinv[u];
    }
}

// ---------- launch: chunk-pipelined PPR + forked KNN chain ----------
extern "C" void kernel_launch(void* const* d_in, const int* in_sizes, int n_in,
                              void* d_out, int out_size) {
    const float* fu = (const float*)d_in[0];
    const float* fi = (const float*)d_in[1];
    const float* r  = (const float*)d_in[2];
    float* out = (float*)d_out;

    static cudaStream_t s2 = 0;
    static cudaEvent_t evF = 0, evZ = 0, evJ = 0, evD = 0, evJ2 = 0, evK = 0;
    static cudaEvent_t evT[NCHUNK] = {0, 0, 0, 0};
    if (!s2) {
        cudaStreamCreateWithFlags(&s2, cudaStreamNonBlocking);
        cudaEventCreateWithFlags(&evF, cudaEventDisableTiming);
        cudaEventCreateWithFlags(&evZ, cudaEventDisableTiming);
        cudaEventCreateWithFlags(&evJ, cudaEventDisableTiming);
        cudaEventCreateWithFlags(&evD, cudaEventDisableTiming);
        cudaEventCreateWithFlags(&evJ2, cudaEventDisableTiming);
        cudaEventCreateWithFlags(&evK, cudaEventDisableTiming);
        for (int c = 0; c < NCHUNK; ++c) cudaEventCreateWithFlags(&evT[c], cudaEventDisableTiming);
    }

    zero_counts_kernel<<<32, 256>>>();

    // fork: zero_piA + KNN chain on s2
    cudaEventRecord(evF, 0);
    cudaStreamWaitEvent(s2, evF, 0);
    zero_piA_kernel<<<2048, 256, 0, s2>>>();
    cudaEventRecord(evZ, s2);
    normalize_kernel<<<NN, 128, 0, s2>>>(fu, fi);
    dim3 gs(32, 32);
    syrk_kernel<<<gs, 256, 0, s2>>>(0);
    knn_topk_kernel<<<NU, 256, 0, s2>>>(0);
    syrk_kernel<<<gs, 256, 0, s2>>>(NU);
    knn_topk_kernel<<<NI, 256, 0, s2>>>(NU);
    knn_sum_kernel<<<NN / 8, 256, 0, s2>>>();
    cudaEventRecord(evJ, s2);

    // PPR prerequisites on main
    build_lists_kernel<<<NU, 256>>>(r);
    invdeg_kernel<<<32, 256>>>();
    cudaStreamWaitEvent(0, evZ, 0);

    // chunk-pipelined PPR: main runs compute stages, s2 picks up top-k per chunk
    for (int c = 0; c < NCHUNK; ++c) {
        int ub = c * UCH;
        pi2_build_kernel<<<UCH, 256>>>(ub);
        ppr_step_kernel<<<NN, 256>>>(0, 0, ub);   // pi2 -> pi3 (chunk)
        ppr_step_kernel<<<NN, 256>>>(1, 0, ub);   // pi3 -> pi4 (chunk)
        ppr_item_T_kernel<<<dim3(NI / 32, UCH / 128), 256>>>(ub);  // pi4 -> scores (chunk)
        cudaEventRecord(evT[c], 0);
        cudaStreamWaitEvent(s2, evT[c], 0);
        ppr_topk_kernel<<<UCH, 256, 0, s2>>>(ub);
    }
    cudaEventRecord(evK, s2);

    // join: knn chain already ordered before topk on s2; wait all of s2
    cudaStreamWaitEvent(0, evK, 0);
    cudaStreamWaitEvent(0, evJ, 0);
    dinv_kernel<<<32, 256>>>();
    cudaEventRecord(evD, 0);

    // parallel tail: user rows on main, item rows on s2
    cudaStreamWaitEvent(s2, evD, 0);
    write_item_kernel<<<NI, 256, 0, s2>>>(out);
    extra_IU_kernel<<<NU, 32, 0, s2>>>(out);
    cudaEventRecord(evJ2, s2);

    write_user_kernel<<<NU, 256>>>(out);
    cudaStreamWaitEvent(0, evJ2, 0);
}

// round 15
// speedup vs baseline: 1.0239x; 1.0239x over previous
#include <cuda_runtime.h>
#include <math.h>

#define NU 4096
#define NI 4096
#define NN 8192
#define D  128
#define KNN 10
#define PPRK 20
#define MAXDEG 256
#define KCAP 128
#define DEGCAP 96
#define DELTA 0.15f
#define ONEM  0.85f

// ---------- static device scratch ----------
__device__ float g_xn[(size_t)NN * D];
__device__ float g_sim[(size_t)NU * NI];       // knn chain only
__device__ float g_scores[(size_t)NU * NI];    // ppr chain only
__device__ float g_piA[(size_t)NN * NU];
__device__ float g_piB[(size_t)NN * NU];
__device__ int   g_uitems[NU * MAXDEG];
__device__ int   g_iusers[NI * MAXDEG];
__device__ int   g_ucnt[NU];
__device__ int   g_icnt[NI];
__device__ float g_invdeg[NN];
__device__ float g_dinv[NN];
// knn edge lists (global node ids in col)
__device__ int   g_knn_cnt[NN];
__device__ int   g_knn_col[(size_t)NN * KCAP];
__device__ float g_knn_w[(size_t)NN * KCAP];
__device__ float g_knnsum[NN];
// ppr extra edges (user-side only; item-side is a scatter)
__device__ int   g_extra_it[NU * PPRK];
__device__ float g_extra_w[NU * PPRK];
__device__ float g_extra_isum[NI];

// ---------- zero all counters ----------
__global__ void zero_counts_kernel() {
    int i = blockIdx.x * 256 + threadIdx.x;   // 0..8191
    g_knn_cnt[i] = 0;
    if (i < NU) g_ucnt[i] = 0;
    if (i < NI) {
        g_icnt[i] = 0;
        g_extra_isum[i] = 0.0f;
    }
}

// ---------- row-normalize features ----------
__global__ void normalize_kernel(const float* __restrict__ fu, const float* __restrict__ fi) {
    int row = blockIdx.x;
    int t = threadIdx.x; // 128 threads
    const float* src = (row < NU) ? &fu[(size_t)row * D] : &fi[(size_t)(row - NU) * D];
    float v = src[t];
    float s = v * v;
    #pragma unroll
    for (int o = 16; o; o >>= 1) s += __shfl_xor_sync(0xffffffff, s, o);
    __shared__ float ws[4];
    if ((t & 31) == 0) ws[t >> 5] = s;
    __syncthreads();
    float tot = ws[0] + ws[1] + ws[2] + ws[3];
    g_xn[(size_t)row * D + t] = v / fmaxf(sqrtf(tot), 1e-12f);
}

// ---------- SYRK: sim = Xn Xn^T (streaming stores; don't pollute L2) ----------
__global__ void __launch_bounds__(256) syrk_kernel(int base) {
    int bm = blockIdx.y * 128, bn = blockIdx.x * 128;
    if (bn < bm) return;
    __shared__ float As[16][132];
    __shared__ float Bs[16][132];
    int tid = threadIdx.x;
    int tx = tid & 15, ty = tid >> 4;
    const float* X = g_xn + (size_t)base * D;
    float acc[8][8] = {};
    for (int k0 = 0; k0 < D; k0 += 16) {
        #pragma unroll
        for (int l = 0; l < 2; ++l) {
            int idx = tid * 2 + l;
            int rr  = idx >> 2;
            int c4  = (idx & 3) * 4;
            float4 a = *(const float4*)&X[(size_t)(bm + rr) * D + k0 + c4];
            As[c4 + 0][rr] = a.x; As[c4 + 1][rr] = a.y;
            As[c4 + 2][rr] = a.z; As[c4 + 3][rr] = a.w;
            float4 b = *(const float4*)&X[(size_t)(bn + rr) * D + k0 + c4];
            Bs[c4 + 0][rr] = b.x; Bs[c4 + 1][rr] = b.y;
            Bs[c4 + 2][rr] = b.z; Bs[c4 + 3][rr] = b.w;
        }
        __syncthreads();
        #pragma unroll
        for (int k = 0; k < 16; ++k) {
            float a[8], b[8];
            *(float4*)&a[0] = *(const float4*)&As[k][ty * 8];
            *(float4*)&a[4] = *(const float4*)&As[k][ty * 8 + 4];
            *(float4*)&b[0] = *(const float4*)&Bs[k][tx * 8];
            *(float4*)&b[4] = *(const float4*)&Bs[k][tx * 8 + 4];
            #pragma unroll
            for (int i = 0; i < 8; ++i)
                #pragma unroll
                for (int j = 0; j < 8; ++j) acc[i][j] = fmaf(a[i], b[j], acc[i][j]);
        }
        __syncthreads();
    }
    #pragma unroll
    for (int i = 0; i < 8; ++i) {
        size_t ro = (size_t)(bm + ty * 8 + i) * NI + bn + tx * 8;
        __stcs((float4*)&g_sim[ro],     make_float4(acc[i][0], acc[i][1], acc[i][2], acc[i][3]));
        __stcs((float4*)&g_sim[ro + 4], make_float4(acc[i][4], acc[i][5], acc[i][6], acc[i][7]));
    }
    if (bm != bn) {
        #pragma unroll
        for (int j = 0; j < 8; ++j) {
            size_t ro = (size_t)(bn + tx * 8 + j) * NI + bm + ty * 8;
            __stcs((float4*)&g_sim[ro],     make_float4(acc[0][j], acc[1][j], acc[2][j], acc[3][j]));
            __stcs((float4*)&g_sim[ro + 4], make_float4(acc[4][j], acc[5][j], acc[6][j], acc[7][j]));
        }
    }
}

// ---------- KNN top-K with cached per-thread argmax; edges to lists ----------
__global__ void __launch_bounds__(256) knn_topk_kernel(int base) {
    int row = blockIdx.x, t = threadIdx.x;
    float v[16];
    const float* srow = g_sim + (size_t)row * NI;
    #pragma unroll
    for (int p = 0; p < 16; ++p) {
        int c = t + p * 256;
        float x = __ldcs(&srow[c]);
        v[p] = (c == row) ? -INFINITY : x;
    }
    float bv = v[0]; int bp = 0;
    #pragma unroll
    for (int p = 1; p < 16; ++p) if (v[p] > bv) { bv = v[p]; bp = p; }

    __shared__ float swv[8];
    __shared__ int   swi[8];
    __shared__ int   bsel;
    for (int k = 0; k < KNN; ++k) {
        float wv = bv; int wc = t + bp * 256;
        #pragma unroll
        for (int o = 16; o; o >>= 1) {
            float ov = __shfl_xor_sync(0xffffffff, wv, o);
            int   oc = __shfl_xor_sync(0xffffffff, wc, o);
            if (ov > wv || (ov == wv && oc < wc)) { wv = ov; wc = oc; }
        }
        if ((t & 31) == 0) { swv[t >> 5] = wv; swi[t >> 5] = wc; }
        __syncthreads();
        if (t == 0) {
            float BV = swv[0]; int BC = swi[0];
            #pragma unroll
            for (int w = 1; w < 8; ++w)
                if (swv[w] > BV || (swv[w] == BV && swi[w] < BC)) { BV = swv[w]; BC = swi[w]; }
            bsel = BC;
            float wgt = fminf(fmaxf((BV + 1.0f) * 0.5f, 1e-6f), 1.0f);
            int gi = base + row, gj = base + BC;
            int a = atomicAdd(&g_knn_cnt[gi], 1);
            if (a < KCAP) { g_knn_col[(size_t)gi * KCAP + a] = gj; g_knn_w[(size_t)gi * KCAP + a] = wgt; }
            int b = atomicAdd(&g_knn_cnt[gj], 1);
            if (b < KCAP) { g_knn_col[(size_t)gj * KCAP + b] = gi; g_knn_w[(size_t)gj * KCAP + b] = wgt; }
        }
        __syncthreads();
        int sc = bsel;
        if ((sc & 255) == t) {
            v[sc >> 8] = -INFINITY;
            bv = v[0]; bp = 0;
            #pragma unroll
            for (int p = 1; p < 16; ++p) if (v[p] > bv) { bv = v[p]; bp = p; }
        }
    }
}

// ---------- bipartite adjacency lists (float4 reads) ----------
__global__ void build_lists_kernel(const float* __restrict__ r) {
    int u = blockIdx.x, t = threadIdx.x;
    __shared__ int scnt;
    if (t == 0) scnt = 0;
    __syncthreads();
    const float4* rr = (const float4*)(r + (size_t)u * NI);
    for (int c4 = t; c4 < NI / 4; c4 += 256) {
        float4 x = __ldcs(&rr[c4]);
        #pragma unroll
        for (int b = 0; b < 4; ++b) {
            float xv = (b == 0) ? x.x : (b == 1) ? x.y : (b == 2) ? x.z : x.w;
            if (xv > 0.0f) {
                int c = c4 * 4 + b;
                int p = atomicAdd(&scnt, 1);
                if (p < MAXDEG) g_uitems[u * MAXDEG + p] = c;
                int q = atomicAdd(&g_icnt[c], 1);
                if (q < MAXDEG) g_iusers[c * MAXDEG + q] = u;
            }
        }
    }
    __syncthreads();
    if (t == 0) g_ucnt[u] = scnt;
}

__global__ void invdeg_kernel() {
    int j = blockIdx.x * 256 + threadIdx.x;
    if (j < NN) {
        int c = (j < NU) ? g_ucnt[j] : g_icnt[j - NU];
        g_invdeg[j] = 1.0f / (float)(c + 1);
    }
}

__global__ void zero_piA_kernel() {
    size_t i = (size_t)blockIdx.x * 256 + threadIdx.x;
    float4 z = make_float4(0.f, 0.f, 0.f, 0.f);
    float4* p = (float4*)g_piA;
    size_t total = (size_t)NN * NU / 4;
    for (size_t k = i; k < total; k += (size_t)gridDim.x * 256) p[k] = z;
}

// ---------- build pi2 analytically ----------
__global__ void pi2_build_kernel() {
    int u = blockIdx.x, t = threadIdx.x;
    int lane = t & 31, wid = t >> 5;
    __shared__ int items[MAXDEG];
    __shared__ int du_s;
    if (t == 0) du_s = min(g_ucnt[u], MAXDEG);
    __syncthreads();
    int d = du_s;
    for (int l = t; l < d; l += 256) items[l] = g_uitems[u * MAXDEG + l];
    __syncthreads();
    float duv = g_invdeg[u];
    float v0 = 0.85f * duv + 0.15f;
    float vI = 0.85f * duv;
    if (t == 0) atomicAdd(&g_piA[(size_t)u * NU + u], 0.85f * v0 * duv + 0.15f);
    for (int l = t; l < d; l += 256) {
        int m = NU + items[l];
        atomicAdd(&g_piA[(size_t)m * NU + u], 0.85f * v0 * duv);
    }
    for (int l = wid; l < d; l += 8) {
        int it = items[l];
        float div = g_invdeg[NU + it];
        float add = 0.85f * vI * div;
        if (lane == 0) atomicAdd(&g_piA[(size_t)(NU + it) * NU + u], add);
        int cj = min(g_icnt[it], MAXDEG);
        for (int q = lane; q < cj; q += 32) {
            int up = g_iusers[it * MAXDEG + q];
            atomicAdd(&g_piA[(size_t)up * NU + u], add);
        }
    }
}

// ---------- dense PPR step, u-chunked (1024 columns per launch) ----------
__global__ void __launch_bounds__(256) ppr_step_kernel(int flip, int jbase, int ubase) {
    const float* __restrict__ pin = flip ? g_piB : g_piA;
    float* __restrict__ pout      = flip ? g_piA : g_piB;
    int j = jbase + blockIdx.x;
    int t = threadIdx.x;
    __shared__ int   nbr[MAXDEG];
    __shared__ float nw[MAXDEG];
    __shared__ int   Ls;
    if (t == 0) Ls = min((j < NU) ? g_ucnt[j] : g_icnt[j - NU], MAXDEG);
    __syncthreads();
    int L = Ls;
    if (j < NU) { if (t < L) nbr[t] = NU + g_uitems[j * MAXDEG + t]; }
    else        { if (t < L) nbr[t] = g_iusers[(j - NU) * MAXDEG + t]; }
    __syncthreads();
    if (t < L) nw[t] = g_invdeg[nbr[t]];
    __syncthreads();

    int u0 = ubase + t * 4;
    float dj = g_invdeg[j];
    float4 p = *(const float4*)(pin + (size_t)j * NU + u0);
    float ax = p.x * dj, ay = p.y * dj, az = p.z * dj, aw = p.w * dj;
    for (int l = 0; l < L; ++l) {
        float4 q = *(const float4*)(pin + (size_t)nbr[l] * NU + u0);
        float w = nw[l];
        ax = fmaf(q.x, w, ax); ay = fmaf(q.y, w, ay);
        az = fmaf(q.z, w, az); aw = fmaf(q.w, w, aw);
    }
    ax *= ONEM; ay *= ONEM; az *= ONEM; aw *= ONEM;
    if (j < NU) {
        int du = j - u0;
        if (du == 0) ax += DELTA;
        else if (du == 1) ay += DELTA;
        else if (du == 2) az += DELTA;
        else if (du == 3) aw += DELTA;
    }
    *(float4*)(pout + (size_t)j * NU + u0) = make_float4(ax, ay, az, aw);
}

// ---------- fused final PPR step (item rows) + in-tile mask + transpose ----------
// grid: (NI/32, uspan/128). Streaming score stores protect pi4's L2 residency.
__global__ void __launch_bounds__(256) ppr_item_T_kernel(int ubase) {
    int i0 = blockIdx.x * 32;
    int u0 = ubase + blockIdx.y * 128;
    int t = threadIdx.x;
    int w = t >> 5, lane = t & 31;
    __shared__ int   sdeg[32];
    __shared__ int   snbr[32][DEGCAP];
    __shared__ float snw[32][DEGCAP];
    __shared__ float stile[32][132];
    if (t < 32) sdeg[t] = min(g_icnt[i0 + t], DEGCAP);
    __syncthreads();
    for (int idx = t; idx < 32 * DEGCAP; idx += 256) {
        int rr = idx / DEGCAP, l = idx - rr * DEGCAP;
        if (l < sdeg[rr]) {
            int up = g_iusers[(i0 + rr) * MAXDEG + l];
            snbr[rr][l] = up;
            snw[rr][l]  = g_invdeg[up];
        }
    }
    __syncthreads();
    const float* __restrict__ pin = g_piA;
    for (int rr = w; rr < 32; rr += 8) {
        int j = NU + i0 + rr;
        float dj = g_invdeg[j];
        float4 p = *(const float4*)(pin + (size_t)j * NU + u0 + lane * 4);
        float ax = p.x * dj, ay = p.y * dj, az = p.z * dj, aw = p.w * dj;
        int L = sdeg[rr];
        for (int l = 0; l < L; ++l) {
            float4 q = *(const float4*)(pin + (size_t)snbr[rr][l] * NU + u0 + lane * 4);
            float wl = snw[rr][l];
            ax = fmaf(q.x, wl, ax); ay = fmaf(q.y, wl, ay);
            az = fmaf(q.z, wl, az); aw = fmaf(q.w, wl, aw);
        }
        stile[rr][lane * 4 + 0] = ax * ONEM;
        stile[rr][lane * 4 + 1] = ay * ONEM;
        stile[rr][lane * 4 + 2] = az * ONEM;
        stile[rr][lane * 4 + 3] = aw * ONEM;
    }
    __syncthreads();
    for (int rr = w; rr < 32; rr += 8) {
        int L = sdeg[rr];
        for (int l = lane; l < L; l += 32) {
            int up = snbr[rr][l];
            int du = up - u0;
            if (du >= 0 && du < 128) stile[rr][du] = -INFINITY;
        }
    }
    __syncthreads();
    int ur = t >> 1, part = t & 1;
    float vals[16];
    #pragma unroll
    for (int c = 0; c < 16; ++c) vals[c] = stile[part * 16 + c][ur];
    float4* dst = (float4*)(g_scores + (size_t)(u0 + ur) * NI + i0 + part * 16);
    __stcs(&dst[0], make_float4(vals[0], vals[1], vals[2], vals[3]));
    __stcs(&dst[1], make_float4(vals[4], vals[5], vals[6], vals[7]));
    __stcs(&dst[2], make_float4(vals[8], vals[9], vals[10], vals[11]));
    __stcs(&dst[3], make_float4(vals[12], vals[13], vals[14], vals[15]));
}

// ---------- PPR top-K -> user-side extra edge lists ----------
__global__ void __launch_bounds__(256) ppr_topk_kernel(int ubase) {
    int u = ubase + blockIdx.x, t = threadIdx.x;
    float v[16];
    const float* srow = g_scores + (size_t)u * NI;
    #pragma unroll
    for (int p = 0; p < 16; ++p) v[p] = __ldcs(&srow[t + p * 256]);
    float bv = v[0]; int bp = 0;
    #pragma unroll
    for (int p = 1; p < 16; ++p) if (v[p] > bv) { bv = v[p]; bp = p; }

    __shared__ float swv[8];
    __shared__ int   swi[8];
    __shared__ float selv[PPRK];
    __shared__ int   seli[PPRK];
    __shared__ int   bsel;
    for (int k = 0; k < PPRK; ++k) {
        float wv = bv; int wc = t + bp * 256;
        #pragma unroll
        for (int o = 16; o; o >>= 1) {
            float ov = __shfl_xor_sync(0xffffffff, wv, o);
            int   oc = __shfl_xor_sync(0xffffffff, wc, o);
            if (ov > wv || (ov == wv && oc < wc)) { wv = ov; wc = oc; }
        }
        if ((t & 31) == 0) { swv[t >> 5] = wv; swi[t >> 5] = wc; }
        __syncthreads();
        if (t == 0) {
            float BV = swv[0]; int BC = swi[0];
            #pragma unroll
            for (int w = 1; w < 8; ++w)
                if (swv[w] > BV || (swv[w] == BV && swi[w] < BC)) { BV = swv[w]; BC = swi[w]; }
            selv[k] = BV; seli[k] = BC; bsel = BC;
        }
        __syncthreads();
        int sc = bsel;
        if ((sc & 255) == t) {
            v[sc >> 8] = -INFINITY;
            bv = v[0]; bp = 0;
            #pragma unroll
            for (int p = 1; p < 16; ++p) if (v[p] > bv) { bv = v[p]; bp = p; }
        }
    }
    if (t < PPRK) {
        float w  = fmaxf(selv[t], 0.0f);
        float mx = fmaxf(selv[0], 0.0f);
        if (mx > 0.0f) w = w / fmaxf(mx, 1e-12f);
        int it = seli[t];
        g_extra_it[u * PPRK + t] = it;
        g_extra_w[u * PPRK + t]  = w;
        atomicAdd(&g_extra_isum[it], w);
    }
}

// ---------- dedup'd KNN list sums (one warp per node) ----------
__global__ void knn_sum_kernel() {
    int node = blockIdx.x * 8 + (threadIdx.x >> 5);
    int lane = threadIdx.x & 31;
    int c = min(g_knn_cnt[node], KCAP);
    const int*   col = g_knn_col + (size_t)node * KCAP;
    const float* w   = g_knn_w   + (size_t)node * KCAP;
    float s = 0.0f;
    for (int e = lane; e < c; e += 32) {
        int cc = col[e];
        bool dup = false;
        for (int q = 0; q < e; ++q) if (col[q] == cc) { dup = true; break; }
        if (!dup) s += w[e];
    }
    #pragma unroll
    for (int o = 16; o; o >>= 1) s += __shfl_xor_sync(0xffffffff, s, o);
    if (lane == 0) g_knnsum[node] = s;
}

// ---------- total rowsum -> dinv (r sums = counts, since r is binary) ----------
__global__ void dinv_kernel() {
    int i = blockIdx.x * 256 + threadIdx.x;   // 0..8191
    float s = g_knnsum[i];
    if (i < NU) {
        s += (float)g_ucnt[i];
        #pragma unroll
        for (int k = 0; k < PPRK; ++k) s += g_extra_w[i * PPRK + k];
    } else {
        s += (float)g_icnt[i - NU] + g_extra_isum[i - NU];
    }
    g_dinv[i] = (s > 0.0f) ? rsqrtf(fmaxf(s, 1e-12f)) : 0.0f;
}

// ---------- write user rows (full row, scaled; no r read) ----------
__global__ void __launch_bounds__(256) write_user_kernel(float* __restrict__ out) {
    int u = blockIdx.x, t = threadIdx.x;
    __shared__ float bufUU[NU];
    __shared__ float bufUI[NI];
    float4 z = make_float4(0.f, 0.f, 0.f, 0.f);
    #pragma unroll
    for (int q = t; q < NU / 4; q += 256) { ((float4*)bufUU)[q] = z; ((float4*)bufUI)[q] = z; }
    __syncthreads();
    int c = min(g_knn_cnt[u], KCAP);
    for (int l = t; l < c; l += 256) bufUU[g_knn_col[(size_t)u * KCAP + l]] = g_knn_w[(size_t)u * KCAP + l];
    int d = min(g_ucnt[u], MAXDEG);
    for (int l = t; l < d; l += 256) bufUI[g_uitems[u * MAXDEG + l]] = 1.0f;
    if (t < PPRK) bufUI[g_extra_it[u * PPRK + t]] = g_extra_w[u * PPRK + t];
    __syncthreads();
    float du = g_dinv[u];
    size_t rowo = (size_t)u * NN;
    for (int q = t; q < NU / 4; q += 256) {
        float4 b  = ((float4*)bufUU)[q];
        float4 dv = *(const float4*)&g_dinv[q * 4];
        ((float4*)&out[rowo])[q] = make_float4(b.x * du * dv.x, b.y * du * dv.y,
                                               b.z * du * dv.z, b.w * du * dv.w);
    }
    for (int q = t; q < NI / 4; q += 256) {
        float4 b  = ((float4*)bufUI)[q];
        float4 dv = *(const float4*)&g_dinv[NU + q * 4];
        ((float4*)&out[rowo + NU])[q] = make_float4(b.x * du * dv.x, b.y * du * dv.y,
                                                    b.z * du * dv.z, b.w * du * dv.w);
    }
}

// ---------- write item rows (IU from rated users; extras patched after) ----------
__global__ void __launch_bounds__(256) write_item_kernel(float* __restrict__ out) {
    int i = blockIdx.x, t = threadIdx.x;
    int node = NU + i;
    __shared__ float bufIU[NU];
    __shared__ float bufII[NI];
    float4 z = make_float4(0.f, 0.f, 0.f, 0.f);
    #pragma unroll
    for (int q = t; q < NU / 4; q += 256) { ((float4*)bufIU)[q] = z; ((float4*)bufII)[q] = z; }
    __syncthreads();
    int c = min(g_knn_cnt[node], KCAP);
    for (int l = t; l < c; l += 256)
        bufII[g_knn_col[(size_t)node * KCAP + l] - NU] = g_knn_w[(size_t)node * KCAP + l];
    int d = min(g_icnt[i], MAXDEG);
    for (int l = t; l < d; l += 256) bufIU[g_iusers[i * MAXDEG + l]] = 1.0f;
    __syncthreads();
    float dn = g_dinv[node];
    size_t rowo = (size_t)node * NN;
    for (int q = t; q < NU / 4; q += 256) {
        float4 b  = ((float4*)bufIU)[q];
        float4 dv = *(const float4*)&g_dinv[q * 4];
        ((float4*)&out[rowo])[q] = make_float4(b.x * dn * dv.x, b.y * dn * dv.y,
                                               b.z * dn * dv.z, b.w * dn * dv.w);
    }
    for (int q = t; q < NI / 4; q += 256) {
        float4 b  = ((float4*)bufII)[q];
        float4 dv = *(const float4*)&g_dinv[NU + q * 4];
        ((float4*)&out[rowo + NU])[q] = make_float4(b.x * dn * dv.x, b.y * dn * dv.y,
                                                    b.z * dn * dv.z, b.w * dn * dv.w);
    }
}

// ---------- scatter extras into IU quadrant (user-side, uncapped) ----------
__global__ void extra_IU_kernel(float* __restrict__ out) {
    int u = blockIdx.x, t = threadIdx.x;
    if (t < PPRK) {
        int it = g_extra_it[u * PPRK + t];
        float w = g_extra_w[u * PPRK + t];
        out[(size_t)(NU + it) * NN + u] = w * g_dinv[NU + it] * g_dinv[u];
    }
}

// ---------- launch: R13 schedule + split item_T with overlapped topk ----------
extern "C" void kernel_launch(void* const* d_in, const int* in_sizes, int n_in,
                              void* d_out, int out_size) {
    const float* fu = (const float*)d_in[0];
    const float* fi = (const float*)d_in[1];
    const float* r  = (const float*)d_in[2];
    float* out = (float*)d_out;

    static cudaStream_t s2 = 0;
    static cudaEvent_t evF = 0, evZ = 0, evJ = 0, evD = 0, evJ2 = 0, evK = 0;
    static cudaEvent_t evT0 = 0, evT1 = 0;
    if (!s2) {
        cudaStreamCreateWithFlags(&s2, cudaStreamNonBlocking);
        cudaEventCreateWithFlags(&evF, cudaEventDisableTiming);
        cudaEventCreateWithFlags(&evZ, cudaEventDisableTiming);
        cudaEventCreateWithFlags(&evJ, cudaEventDisableTiming);
        cudaEventCreateWithFlags(&evD, cudaEventDisableTiming);
        cudaEventCreateWithFlags(&evJ2, cudaEventDisableTiming);
        cudaEventCreateWithFlags(&evK, cudaEventDisableTiming);
        cudaEventCreateWithFlags(&evT0, cudaEventDisableTiming);
        cudaEventCreateWithFlags(&evT1, cudaEventDisableTiming);
    }

    zero_counts_kernel<<<32, 256>>>();

    // fork: zero_piA + KNN chain on s2
    cudaEventRecord(evF, 0);
    cudaStreamWaitEvent(s2, evF, 0);
    zero_piA_kernel<<<2048, 256, 0, s2>>>();
    cudaEventRecord(evZ, s2);
    normalize_kernel<<<NN, 128, 0, s2>>>(fu, fi);
    dim3 gs(32, 32);
    syrk_kernel<<<gs, 256, 0, s2>>>(0);
    knn_topk_kernel<<<NU, 256, 0, s2>>>(0);
    syrk_kernel<<<gs, 256, 0, s2>>>(NU);
    knn_topk_kernel<<<NI, 256, 0, s2>>>(NU);
    knn_sum_kernel<<<NN / 8, 256, 0, s2>>>();
    cudaEventRecord(evJ, s2);

    // PPR chain on origin stream (phase-ordered, as in R13)
    build_lists_kernel<<<NU, 256>>>(r);
    invdeg_kernel<<<32, 256>>>();
    cudaStreamWaitEvent(0, evZ, 0);
    pi2_build_kernel<<<NU, 256>>>();

    for (int c = 0; c < 4; ++c) ppr_step_kernel<<<NN, 256>>>(0, 0, c * 1024);   // pi2->pi3
    for (int c = 0; c < 4; ++c) ppr_step_kernel<<<NN, 256>>>(1, 0, c * 1024);   // pi3->pi4

    // item_T split in 2 u-halves; topk(half) overlapped on s2
    ppr_item_T_kernel<<<dim3(NI / 32, 16), 256>>>(0);
    cudaEventRecord(evT0, 0);
    cudaStreamWaitEvent(s2, evT0, 0);
    ppr_topk_kernel<<<2048, 256, 0, s2>>>(0);
    ppr_item_T_kernel<<<dim3(NI / 32, 16), 256>>>(2048);
    cudaEventRecord(evT1, 0);
    cudaStreamWaitEvent(s2, evT1, 0);
    ppr_topk_kernel<<<2048, 256, 0, s2>>>(2048);
    cudaEventRecord(evK, s2);

    // join (evK covers evJ by s2 ordering; keep both for clarity)
    cudaStreamWaitEvent(0, evK, 0);
    cudaStreamWaitEvent(0, evJ, 0);
    dinv_kernel<<<32, 256>>>();
    cudaEventRecord(evD, 0);

    // parallel tail: user rows on main, item rows on s2
    cudaStreamWaitEvent(s2, evD, 0);
    write_item_kernel<<<NI, 256, 0, s2>>>(out);
    extra_IU_kernel<<<NU, 32, 0, s2>>>(out);
    cudaEventRecord(evJ2, s2);

    write_user_kernel<<<NU, 256>>>(out);
    cudaStreamWaitEvent(0, evJ2, 0);
}

// round 16
// speedup vs baseline: 1.0306x; 1.0066x over previous
#include <cuda_runtime.h>
#include <math.h>

#define NU 4096
#define NI 4096
#define NN 8192
#define D  128
#define KNN 10
#define PPRK 20
#define MAXDEG 256
#define KCAP 128
#define DEGCAP 96
#define DELTA 0.15f
#define ONEM  0.85f

// ---------- static device scratch ----------
__device__ float g_xn[(size_t)NN * D];
__device__ float g_sim[(size_t)NU * NI];       // knn chain only
__device__ float g_scores[(size_t)NU * NI];    // ppr chain only
__device__ float g_piA[(size_t)NN * NU];
__device__ float g_piB[(size_t)NN * NU];
__device__ int   g_uitems[NU * MAXDEG];
__device__ int   g_iusers[NI * MAXDEG];
__device__ int   g_ucnt[NU];
__device__ int   g_icnt[NI];
__device__ float g_invdeg[NN];
__device__ float g_dinv[NN];
// knn edge lists (global node ids in col)
__device__ int   g_knn_cnt[NN];
__device__ int   g_knn_col[(size_t)NN * KCAP];
__device__ float g_knn_w[(size_t)NN * KCAP];
__device__ float g_knnsum[NN];
// ppr extra edges (user-side only; item-side is a scatter)
__device__ int   g_extra_it[NU * PPRK];
__device__ float g_extra_w[NU * PPRK];
__device__ float g_extra_isum[NI];

// ---------- zero all counters ----------
__global__ void zero_counts_kernel() {
    int i = blockIdx.x * 256 + threadIdx.x;   // 0..8191
    g_knn_cnt[i] = 0;
    if (i < NU) g_ucnt[i] = 0;
    if (i < NI) {
        g_icnt[i] = 0;
        g_extra_isum[i] = 0.0f;
    }
}

// ---------- row-normalize features ----------
__global__ void normalize_kernel(const float* __restrict__ fu, const float* __restrict__ fi) {
    int row = blockIdx.x;
    int t = threadIdx.x; // 128 threads
    const float* src = (row < NU) ? &fu[(size_t)row * D] : &fi[(size_t)(row - NU) * D];
    float v = src[t];
    float s = v * v;
    #pragma unroll
    for (int o = 16; o; o >>= 1) s += __shfl_xor_sync(0xffffffff, s, o);
    __shared__ float ws[4];
    if ((t & 31) == 0) ws[t >> 5] = s;
    __syncthreads();
    float tot = ws[0] + ws[1] + ws[2] + ws[3];
    g_xn[(size_t)row * D + t] = v / fmaxf(sqrtf(tot), 1e-12f);
}

// ---------- SYRK: sim = Xn Xn^T (streaming stores; don't pollute L2) ----------
__global__ void __launch_bounds__(256) syrk_kernel(int base) {
    int bm = blockIdx.y * 128, bn = blockIdx.x * 128;
    if (bn < bm) return;
    __shared__ float As[16][132];
    __shared__ float Bs[16][132];
    int tid = threadIdx.x;
    int tx = tid & 15, ty = tid >> 4;
    const float* X = g_xn + (size_t)base * D;
    float acc[8][8] = {};
    for (int k0 = 0; k0 < D; k0 += 16) {
        #pragma unroll
        for (int l = 0; l < 2; ++l) {
            int idx = tid * 2 + l;
            int rr  = idx >> 2;
            int c4  = (idx & 3) * 4;
            float4 a = *(const float4*)&X[(size_t)(bm + rr) * D + k0 + c4];
            As[c4 + 0][rr] = a.x; As[c4 + 1][rr] = a.y;
            As[c4 + 2][rr] = a.z; As[c4 + 3][rr] = a.w;
            float4 b = *(const float4*)&X[(size_t)(bn + rr) * D + k0 + c4];
            Bs[c4 + 0][rr] = b.x; Bs[c4 + 1][rr] = b.y;
            Bs[c4 + 2][rr] = b.z; Bs[c4 + 3][rr] = b.w;
        }
        __syncthreads();
        #pragma unroll
        for (int k = 0; k < 16; ++k) {
            float a[8], b[8];
            *(float4*)&a[0] = *(const float4*)&As[k][ty * 8];
            *(float4*)&a[4] = *(const float4*)&As[k][ty * 8 + 4];
            *(float4*)&b[0] = *(const float4*)&Bs[k][tx * 8];
            *(float4*)&b[4] = *(const float4*)&Bs[k][tx * 8 + 4];
            #pragma unroll
            for (int i = 0; i < 8; ++i)
                #pragma unroll
                for (int j = 0; j < 8; ++j) acc[i][j] = fmaf(a[i], b[j], acc[i][j]);
        }
        __syncthreads();
    }
    #pragma unroll
    for (int i = 0; i < 8; ++i) {
        size_t ro = (size_t)(bm + ty * 8 + i) * NI + bn + tx * 8;
        __stcs((float4*)&g_sim[ro],     make_float4(acc[i][0], acc[i][1], acc[i][2], acc[i][3]));
        __stcs((float4*)&g_sim[ro + 4], make_float4(acc[i][4], acc[i][5], acc[i][6], acc[i][7]));
    }
    if (bm != bn) {
        #pragma unroll
        for (int j = 0; j < 8; ++j) {
            size_t ro = (size_t)(bn + tx * 8 + j) * NI + bm + ty * 8;
            __stcs((float4*)&g_sim[ro],     make_float4(acc[0][j], acc[1][j], acc[2][j], acc[3][j]));
            __stcs((float4*)&g_sim[ro + 4], make_float4(acc[4][j], acc[5][j], acc[6][j], acc[7][j]));
        }
    }
}

// ---------- KNN top-K with cached per-thread argmax; edges to lists ----------
__global__ void __launch_bounds__(256) knn_topk_kernel(int base) {
    int row = blockIdx.x, t = threadIdx.x;
    float v[16];
    const float* srow = g_sim + (size_t)row * NI;
    #pragma unroll
    for (int p = 0; p < 16; ++p) {
        int c = t + p * 256;
        float x = __ldcs(&srow[c]);
        v[p] = (c == row) ? -INFINITY : x;
    }
    float bv = v[0]; int bp = 0;
    #pragma unroll
    for (int p = 1; p < 16; ++p) if (v[p] > bv) { bv = v[p]; bp = p; }

    __shared__ float swv[8];
    __shared__ int   swi[8];
    __shared__ int   bsel;
    for (int k = 0; k < KNN; ++k) {
        float wv = bv; int wc = t + bp * 256;
        #pragma unroll
        for (int o = 16; o; o >>= 1) {
            float ov = __shfl_xor_sync(0xffffffff, wv, o);
            int   oc = __shfl_xor_sync(0xffffffff, wc, o);
            if (ov > wv || (ov == wv && oc < wc)) { wv = ov; wc = oc; }
        }
        if ((t & 31) == 0) { swv[t >> 5] = wv; swi[t >> 5] = wc; }
        __syncthreads();
        if (t == 0) {
            float BV = swv[0]; int BC = swi[0];
            #pragma unroll
            for (int w = 1; w < 8; ++w)
                if (swv[w] > BV || (swv[w] == BV && swi[w] < BC)) { BV = swv[w]; BC = swi[w]; }
            bsel = BC;
            float wgt = fminf(fmaxf((BV + 1.0f) * 0.5f, 1e-6f), 1.0f);
            int gi = base + row, gj = base + BC;
            int a = atomicAdd(&g_knn_cnt[gi], 1);
            if (a < KCAP) { g_knn_col[(size_t)gi * KCAP + a] = gj; g_knn_w[(size_t)gi * KCAP + a] = wgt; }
            int b = atomicAdd(&g_knn_cnt[gj], 1);
            if (b < KCAP) { g_knn_col[(size_t)gj * KCAP + b] = gi; g_knn_w[(size_t)gj * KCAP + b] = wgt; }
        }
        __syncthreads();
        int sc = bsel;
        if ((sc & 255) == t) {
            v[sc >> 8] = -INFINITY;
            bv = v[0]; bp = 0;
            #pragma unroll
            for (int p = 1; p < 16; ++p) if (v[p] > bv) { bv = v[p]; bp = p; }
        }
    }
}

// ---------- bipartite adjacency lists (float4 reads) ----------
__global__ void build_lists_kernel(const float* __restrict__ r) {
    int u = blockIdx.x, t = threadIdx.x;
    __shared__ int scnt;
    if (t == 0) scnt = 0;
    __syncthreads();
    const float4* rr = (const float4*)(r + (size_t)u * NI);
    for (int c4 = t; c4 < NI / 4; c4 += 256) {
        float4 x = __ldcs(&rr[c4]);
        #pragma unroll
        for (int b = 0; b < 4; ++b) {
            float xv = (b == 0) ? x.x : (b == 1) ? x.y : (b == 2) ? x.z : x.w;
            if (xv > 0.0f) {
                int c = c4 * 4 + b;
                int p = atomicAdd(&scnt, 1);
                if (p < MAXDEG) g_uitems[u * MAXDEG + p] = c;
                int q = atomicAdd(&g_icnt[c], 1);
                if (q < MAXDEG) g_iusers[c * MAXDEG + q] = u;
            }
        }
    }
    __syncthreads();
    if (t == 0) g_ucnt[u] = scnt;
}

__global__ void invdeg_kernel() {
    int j = blockIdx.x * 256 + threadIdx.x;
    if (j < NN) {
        int c = (j < NU) ? g_ucnt[j] : g_icnt[j - NU];
        g_invdeg[j] = 1.0f / (float)(c + 1);
    }
}

__global__ void zero_piA_kernel() {
    size_t i = (size_t)blockIdx.x * 256 + threadIdx.x;
    float4 z = make_float4(0.f, 0.f, 0.f, 0.f);
    float4* p = (float4*)g_piA;
    size_t total = (size_t)NN * NU / 4;
    for (size_t k = i; k < total; k += (size_t)gridDim.x * 256) p[k] = z;
}

// ---------- build pi2 analytically ----------
__global__ void pi2_build_kernel() {
    int u = blockIdx.x, t = threadIdx.x;
    int lane = t & 31, wid = t >> 5;
    __shared__ int items[MAXDEG];
    __shared__ int du_s;
    if (t == 0) du_s = min(g_ucnt[u], MAXDEG);
    __syncthreads();
    int d = du_s;
    for (int l = t; l < d; l += 256) items[l] = g_uitems[u * MAXDEG + l];
    __syncthreads();
    float duv = g_invdeg[u];
    float v0 = 0.85f * duv + 0.15f;
    float vI = 0.85f * duv;
    if (t == 0) atomicAdd(&g_piA[(size_t)u * NU + u], 0.85f * v0 * duv + 0.15f);
    for (int l = t; l < d; l += 256) {
        int m = NU + items[l];
        atomicAdd(&g_piA[(size_t)m * NU + u], 0.85f * v0 * duv);
    }
    for (int l = wid; l < d; l += 8) {
        int it = items[l];
        float div = g_invdeg[NU + it];
        float add = 0.85f * vI * div;
        if (lane == 0) atomicAdd(&g_piA[(size_t)(NU + it) * NU + u], add);
        int cj = min(g_icnt[it], MAXDEG);
        for (int q = lane; q < cj; q += 32) {
            int up = g_iusers[it * MAXDEG + q];
            atomicAdd(&g_piA[(size_t)up * NU + u], add);
        }
    }
}

// ---------- dense PPR step, u-chunked; gather loop unrolled x4 for MLP ----------
__global__ void __launch_bounds__(256) ppr_step_kernel(int flip, int jbase, int ubase) {
    const float* __restrict__ pin = flip ? g_piB : g_piA;
    float* __restrict__ pout      = flip ? g_piA : g_piB;
    int j = jbase + blockIdx.x;
    int t = threadIdx.x;
    __shared__ int   nbr[MAXDEG];
    __shared__ float nw[MAXDEG];
    __shared__ int   Ls;
    if (t == 0) Ls = min((j < NU) ? g_ucnt[j] : g_icnt[j - NU], MAXDEG);
    __syncthreads();
    int L = Ls;
    if (j < NU) { if (t < L) nbr[t] = NU + g_uitems[j * MAXDEG + t]; }
    else        { if (t < L) nbr[t] = g_iusers[(j - NU) * MAXDEG + t]; }
    __syncthreads();
    if (t < L) nw[t] = g_invdeg[nbr[t]];
    __syncthreads();

    int u0 = ubase + t * 4;
    float dj = g_invdeg[j];
    float4 p = *(const float4*)(pin + (size_t)j * NU + u0);
    float ax = p.x * dj, ay = p.y * dj, az = p.z * dj, aw = p.w * dj;
    int l = 0;
    for (; l + 4 <= L; l += 4) {
        // batch 4 independent gathers (MLP=4), then accumulate in original order
        float4 q0 = *(const float4*)(pin + (size_t)nbr[l + 0] * NU + u0);
        float4 q1 = *(const float4*)(pin + (size_t)nbr[l + 1] * NU + u0);
        float4 q2 = *(const float4*)(pin + (size_t)nbr[l + 2] * NU + u0);
        float4 q3 = *(const float4*)(pin + (size_t)nbr[l + 3] * NU + u0);
        float w0 = nw[l + 0], w1 = nw[l + 1], w2 = nw[l + 2], w3 = nw[l + 3];
        ax = fmaf(q0.x, w0, ax); ay = fmaf(q0.y, w0, ay);
        az = fmaf(q0.z, w0, az); aw = fmaf(q0.w, w0, aw);
        ax = fmaf(q1.x, w1, ax); ay = fmaf(q1.y, w1, ay);
        az = fmaf(q1.z, w1, az); aw = fmaf(q1.w, w1, aw);
        ax = fmaf(q2.x, w2, ax); ay = fmaf(q2.y, w2, ay);
        az = fmaf(q2.z, w2, az); aw = fmaf(q2.w, w2, aw);
        ax = fmaf(q3.x, w3, ax); ay = fmaf(q3.y, w3, ay);
        az = fmaf(q3.z, w3, az); aw = fmaf(q3.w, w3, aw);
    }
    for (; l < L; ++l) {
        float4 q = *(const float4*)(pin + (size_t)nbr[l] * NU + u0);
        float w = nw[l];
        ax = fmaf(q.x, w, ax); ay = fmaf(q.y, w, ay);
        az = fmaf(q.z, w, az); aw = fmaf(q.w, w, aw);
    }
    ax *= ONEM; ay *= ONEM; az *= ONEM; aw *= ONEM;
    if (j < NU) {
        int du = j - u0;
        if (du == 0) ax += DELTA;
        else if (du == 1) ay += DELTA;
        else if (du == 2) az += DELTA;
        else if (du == 3) aw += DELTA;
    }
    *(float4*)(pout + (size_t)j * NU + u0) = make_float4(ax, ay, az, aw);
}

// ---------- fused final PPR step (item rows) + in-tile mask + transpose ----------
// grid: (NI/32, NU/128). Gather loop unrolled x4; FMA order preserved.
__global__ void __launch_bounds__(256) ppr_item_T_kernel() {
    int i0 = blockIdx.x * 32;
    int u0 = blockIdx.y * 128;
    int t = threadIdx.x;
    int w = t >> 5, lane = t & 31;
    __shared__ int   sdeg[32];
    __shared__ int   snbr[32][DEGCAP];
    __shared__ float snw[32][DEGCAP];
    __shared__ float stile[32][132];
    if (t < 32) sdeg[t] = min(g_icnt[i0 + t], DEGCAP);
    __syncthreads();
    for (int idx = t; idx < 32 * DEGCAP; idx += 256) {
        int rr = idx / DEGCAP, l = idx - rr * DEGCAP;
        if (l < sdeg[rr]) {
            int up = g_iusers[(i0 + rr) * MAXDEG + l];
            snbr[rr][l] = up;
            snw[rr][l]  = g_invdeg[up];
        }
    }
    __syncthreads();
    const float* __restrict__ pin = g_piA;
    for (int rr = w; rr < 32; rr += 8) {
        int j = NU + i0 + rr;
        float dj = g_invdeg[j];
        float4 p = *(const float4*)(pin + (size_t)j * NU + u0 + lane * 4);
        float ax = p.x * dj, ay = p.y * dj, az = p.z * dj, aw = p.w * dj;
        int L = sdeg[rr];
        int l = 0;
        for (; l + 4 <= L; l += 4) {
            float4 q0 = *(const float4*)(pin + (size_t)snbr[rr][l + 0] * NU + u0 + lane * 4);
            float4 q1 = *(const float4*)(pin + (size_t)snbr[rr][l + 1] * NU + u0 + lane * 4);
            float4 q2 = *(const float4*)(pin + (size_t)snbr[rr][l + 2] * NU + u0 + lane * 4);
            float4 q3 = *(const float4*)(pin + (size_t)snbr[rr][l + 3] * NU + u0 + lane * 4);
            float w0 = snw[rr][l + 0], w1 = snw[rr][l + 1];
            float w2 = snw[rr][l + 2], w3 = snw[rr][l + 3];
            ax = fmaf(q0.x, w0, ax); ay = fmaf(q0.y, w0, ay);
            az = fmaf(q0.z, w0, az); aw = fmaf(q0.w, w0, aw);
            ax = fmaf(q1.x, w1, ax); ay = fmaf(q1.y, w1, ay);
            az = fmaf(q1.z, w1, az); aw = fmaf(q1.w, w1, aw);
            ax = fmaf(q2.x, w2, ax); ay = fmaf(q2.y, w2, ay);
            az = fmaf(q2.z, w2, az); aw = fmaf(q2.w, w2, aw);
            ax = fmaf(q3.x, w3, ax); ay = fmaf(q3.y, w3, ay);
            az = fmaf(q3.z, w3, az); aw = fmaf(q3.w, w3, aw);
        }
        for (; l < L; ++l) {
            float4 q = *(const float4*)(pin + (size_t)snbr[rr][l] * NU + u0 + lane * 4);
            float wl = snw[rr][l];
            ax = fmaf(q.x, wl, ax); ay = fmaf(q.y, wl, ay);
            az = fmaf(q.z, wl, az); aw = fmaf(q.w, wl, aw);
        }
        stile[rr][lane * 4 + 0] = ax * ONEM;
        stile[rr][lane * 4 + 1] = ay * ONEM;
        stile[rr][lane * 4 + 2] = az * ONEM;
        stile[rr][lane * 4 + 3] = aw * ONEM;
    }
    __syncthreads();
    for (int rr = w; rr < 32; rr += 8) {
        int L = sdeg[rr];
        for (int l = lane; l < L; l += 32) {
            int up = snbr[rr][l];
            int du = up - u0;
            if (du >= 0 && du < 128) stile[rr][du] = -INFINITY;
        }
    }
    __syncthreads();
    int ur = t >> 1, part = t & 1;
    float vals[16];
    #pragma unroll
    for (int c = 0; c < 16; ++c) vals[c] = stile[part * 16 + c][ur];
    float4* dst = (float4*)(g_scores + (size_t)(u0 + ur) * NI + i0 + part * 16);
    dst[0] = make_float4(vals[0], vals[1], vals[2], vals[3]);
    dst[1] = make_float4(vals[4], vals[5], vals[6], vals[7]);
    dst[2] = make_float4(vals[8], vals[9], vals[10], vals[11]);
    dst[3] = make_float4(vals[12], vals[13], vals[14], vals[15]);
}

// ---------- PPR top-K -> user-side extra edge lists ----------
__global__ void __launch_bounds__(256) ppr_topk_kernel() {
    int u = blockIdx.x, t = threadIdx.x;
    float v[16];
    const float* srow = g_scores + (size_t)u * NI;
    #pragma unroll
    for (int p = 0; p < 16; ++p) v[p] = srow[t + p * 256];
    float bv = v[0]; int bp = 0;
    #pragma unroll
    for (int p = 1; p < 16; ++p) if (v[p] > bv) { bv = v[p]; bp = p; }

    __shared__ float swv[8];
    __shared__ int   swi[8];
    __shared__ float selv[PPRK];
    __shared__ int   seli[PPRK];
    __shared__ int   bsel;
    for (int k = 0; k < PPRK; ++k) {
        float wv = bv; int wc = t + bp * 256;
        #pragma unroll
        for (int o = 16; o; o >>= 1) {
            float ov = __shfl_xor_sync(0xffffffff, wv, o);
            int   oc = __shfl_xor_sync(0xffffffff, wc, o);
            if (ov > wv || (ov == wv && oc < wc)) { wv = ov; wc = oc; }
        }
        if ((t & 31) == 0) { swv[t >> 5] = wv; swi[t >> 5] = wc; }
        __syncthreads();
        if (t == 0) {
            float BV = swv[0]; int BC = swi[0];
            #pragma unroll
            for (int w = 1; w < 8; ++w)
                if (swv[w] > BV || (swv[w] == BV && swi[w] < BC)) { BV = swv[w]; BC = swi[w]; }
            selv[k] = BV; seli[k] = BC; bsel = BC;
        }
        __syncthreads();
        int sc = bsel;
        if ((sc & 255) == t) {
            v[sc >> 8] = -INFINITY;
            bv = v[0]; bp = 0;
            #pragma unroll
            for (int p = 1; p < 16; ++p) if (v[p] > bv) { bv = v[p]; bp = p; }
        }
    }
    if (t < PPRK) {
        float w  = fmaxf(selv[t], 0.0f);
        float mx = fmaxf(selv[0], 0.0f);
        if (mx > 0.0f) w = w / fmaxf(mx, 1e-12f);
        int it = seli[t];
        g_extra_it[u * PPRK + t] = it;
        g_extra_w[u * PPRK + t]  = w;
        atomicAdd(&g_extra_isum[it], w);
    }
}

// ---------- dedup'd KNN list sums (one warp per node) ----------
__global__ void knn_sum_kernel() {
    int node = blockIdx.x * 8 + (threadIdx.x >> 5);
    int lane = threadIdx.x & 31;
    int c = min(g_knn_cnt[node], KCAP);
    const int*   col = g_knn_col + (size_t)node * KCAP;
    const float* w   = g_knn_w   + (size_t)node * KCAP;
    float s = 0.0f;
    for (int e = lane; e < c; e += 32) {
        int cc = col[e];
        bool dup = false;
        for (int q = 0; q < e; ++q) if (col[q] == cc) { dup = true; break; }
        if (!dup) s += w[e];
    }
    #pragma unroll
    for (int o = 16; o; o >>= 1) s += __shfl_xor_sync(0xffffffff, s, o);
    if (lane == 0) g_knnsum[node] = s;
}

// ---------- total rowsum -> dinv (r sums = counts, since r is binary) ----------
__global__ void dinv_kernel() {
    int i = blockIdx.x * 256 + threadIdx.x;   // 0..8191
    float s = g_knnsum[i];
    if (i < NU) {
        s += (float)g_ucnt[i];
        #pragma unroll
        for (int k = 0; k < PPRK; ++k) s += g_extra_w[i * PPRK + k];
    } else {
        s += (float)g_icnt[i - NU] + g_extra_isum[i - NU];
    }
    g_dinv[i] = (s > 0.0f) ? rsqrtf(fmaxf(s, 1e-12f)) : 0.0f;
}

// ---------- write user rows (full row, scaled; no r read) ----------
__global__ void __launch_bounds__(256) write_user_kernel(float* __restrict__ out) {
    int u = blockIdx.x, t = threadIdx.x;
    __shared__ float bufUU[NU];
    __shared__ float bufUI[NI];
    float4 z = make_float4(0.f, 0.f, 0.f, 0.f);
    #pragma unroll
    for (int q = t; q < NU / 4; q += 256) { ((float4*)bufUU)[q] = z; ((float4*)bufUI)[q] = z; }
    __syncthreads();
    int c = min(g_knn_cnt[u], KCAP);
    for (int l = t; l < c; l += 256) bufUU[g_knn_col[(size_t)u * KCAP + l]] = g_knn_w[(size_t)u * KCAP + l];
    int d = min(g_ucnt[u], MAXDEG);
    for (int l = t; l < d; l += 256) bufUI[g_uitems[u * MAXDEG + l]] = 1.0f;
    if (t < PPRK) bufUI[g_extra_it[u * PPRK + t]] = g_extra_w[u * PPRK + t];
    __syncthreads();
    float du = g_dinv[u];
    size_t rowo = (size_t)u * NN;
    for (int q = t; q < NU / 4; q += 256) {
        float4 b  = ((float4*)bufUU)[q];
        float4 dv = *(const float4*)&g_dinv[q * 4];
        ((float4*)&out[rowo])[q] = make_float4(b.x * du * dv.x, b.y * du * dv.y,
                                               b.z * du * dv.z, b.w * du * dv.w);
    }
    for (int q = t; q < NI / 4; q += 256) {
        float4 b  = ((float4*)bufUI)[q];
        float4 dv = *(const float4*)&g_dinv[NU + q * 4];
        ((float4*)&out[rowo + NU])[q] = make_float4(b.x * du * dv.x, b.y * du * dv.y,
                                                    b.z * du * dv.z, b.w * du * dv.w);
    }
}

// ---------- write item rows (IU from rated users; extras patched after) ----------
__global__ void __launch_bounds__(256) write_item_kernel(float* __restrict__ out) {
    int i = blockIdx.x, t = threadIdx.x;
    int node = NU + i;
    __shared__ float bufIU[NU];
    __shared__ float bufII[NI];
    float4 z = make_float4(0.f, 0.f, 0.f, 0.f);
    #pragma unroll
    for (int q = t; q < NU / 4; q += 256) { ((float4*)bufIU)[q] = z; ((float4*)bufII)[q] = z; }
    __syncthreads();
    int c = min(g_knn_cnt[node], KCAP);
    for (int l = t; l < c; l += 256)
        bufII[g_knn_col[(size_t)node * KCAP + l] - NU] = g_knn_w[(size_t)node * KCAP + l];
    int d = min(g_icnt[i], MAXDEG);
    for (int l = t; l < d; l += 256) bufIU[g_iusers[i * MAXDEG + l]] = 1.0f;
    __syncthreads();
    float dn = g_dinv[node];
    size_t rowo = (size_t)node * NN;
    for (int q = t; q < NU / 4; q += 256) {
        float4 b  = ((float4*)bufIU)[q];
        float4 dv = *(const float4*)&g_dinv[q * 4];
        ((float4*)&out[rowo])[q] = make_float4(b.x * dn * dv.x, b.y * dn * dv.y,
                                               b.z * dn * dv.z, b.w * dn * dv.w);
    }
    for (int q = t; q < NI / 4; q += 256) {
        float4 b  = ((float4*)bufII)[q];
        float4 dv = *(const float4*)&g_dinv[NU + q * 4];
        ((float4*)&out[rowo + NU])[q] = make_float4(b.x * dn * dv.x, b.y * dn * dv.y,
                                                    b.z * dn * dv.z, b.w * dn * dv.w);
    }
}

// ---------- scatter extras into IU quadrant (user-side, uncapped) ----------
__global__ void extra_IU_kernel(float* __restrict__ out) {
    int u = blockIdx.x, t = threadIdx.x;
    if (t < PPRK) {
        int it = g_extra_it[u * PPRK + t];
        float w = g_extra_w[u * PPRK + t];
        out[(size_t)(NU + it) * NN + u] = w * g_dinv[NU + it] * g_dinv[u];
    }
}

// ---------- launch: R13 schedule (best) ----------
extern "C" void kernel_launch(void* const* d_in, const int* in_sizes, int n_in,
                              void* d_out, int out_size) {
    const float* fu = (const float*)d_in[0];
    const float* fi = (const float*)d_in[1];
    const float* r  = (const float*)d_in[2];
    float* out = (float*)d_out;

    static cudaStream_t s2 = 0;
    static cudaEvent_t evF = 0, evZ = 0, evJ = 0, evD = 0, evJ2 = 0;
    if (!s2) {
        cudaStreamCreateWithFlags(&s2, cudaStreamNonBlocking);
        cudaEventCreateWithFlags(&evF, cudaEventDisableTiming);
        cudaEventCreateWithFlags(&evZ, cudaEventDisableTiming);
        cudaEventCreateWithFlags(&evJ, cudaEventDisableTiming);
        cudaEventCreateWithFlags(&evD, cudaEventDisableTiming);
        cudaEventCreateWithFlags(&evJ2, cudaEventDisableTiming);
    }

    zero_counts_kernel<<<32, 256>>>();

    // fork: zero_piA + KNN chain on s2
    cudaEventRecord(evF, 0);
    cudaStreamWaitEvent(s2, evF, 0);
    zero_piA_kernel<<<2048, 256, 0, s2>>>();
    cudaEventRecord(evZ, s2);
    normalize_kernel<<<NN, 128, 0, s2>>>(fu, fi);
    dim3 gs(32, 32);
    syrk_kernel<<<gs, 256, 0, s2>>>(0);
    knn_topk_kernel<<<NU, 256, 0, s2>>>(0);
    syrk_kernel<<<gs, 256, 0, s2>>>(NU);
    knn_topk_kernel<<<NI, 256, 0, s2>>>(NU);
    knn_sum_kernel<<<NN / 8, 256, 0, s2>>>();
    cudaEventRecord(evJ, s2);

    // PPR chain on origin stream (phase-ordered)
    build_lists_kernel<<<NU, 256>>>(r);
    invdeg_kernel<<<32, 256>>>();
    cudaStreamWaitEvent(0, evZ, 0);
    pi2_build_kernel<<<NU, 256>>>();

    for (int c = 0; c < 4; ++c) ppr_step_kernel<<<NN, 256>>>(0, 0, c * 1024);   // pi2->pi3
    for (int c = 0; c < 4; ++c) ppr_step_kernel<<<NN, 256>>>(1, 0, c * 1024);   // pi3->pi4
    ppr_item_T_kernel<<<dim3(NI / 32, NU / 128), 256>>>();                      // pi4->pi5 fused + mask + T

    ppr_topk_kernel<<<NU, 256>>>();

    // join knn chain, compute dinv
    cudaStreamWaitEvent(0, evJ, 0);
    dinv_kernel<<<32, 256>>>();
    cudaEventRecord(evD, 0);

    // parallel tail: user rows on main, item rows on s2
    cudaStreamWaitEvent(s2, evD, 0);
    write_item_kernel<<<NI, 256, 0, s2>>>(out);
    extra_IU_kernel<<<NU, 32, 0, s2>>>(out);
    cudaEventRecord(evJ2, s2);

    write_user_kernel<<<NU, 256>>>(out);
    cudaStreamWaitEvent(0, evJ2, 0);
}